// round 9
// baseline (speedup 1.0000x reference)
#include <cuda_runtime.h>
#include <cuda_fp16.h>

#define N_NODES 100000
#define N_EDGES 500000
#define IN_DIM 16
#define HEADS 4
#define OUT_DIM 128
#define HC 512           // HEADS*OUT_DIM
#define NEG 0.2f

// Scratch (device globals: allocation-free per harness rules)
__device__ __half g_xl[(size_t)N_NODES * HC];    // 102.4 MB
__device__ __half g_xr[(size_t)N_NODES * HC];    // 102.4 MB
__device__ float  g_ex[(size_t)N_EDGES * HEADS]; // 8 MB, CSR slot order
__device__ int    g_counts[N_NODES];
__device__ int    g_row[N_NODES + 1];
__device__ int    g_cursor[N_NODES];
__device__ int    g_srcs[N_EDGES];               // CSR: src per slot
__device__ int    g_dsts[N_EDGES];               // CSR: dst per slot

__device__ __forceinline__ float lrelu(float v) { return v > 0.f ? v : NEG * v; }

// packed f32x2 helpers (sm_103a; ptxas never auto-fuses these)
__device__ __forceinline__ unsigned long long pack2(float lo, float hi) {
    unsigned long long r;
    asm("mov.b64 %0, {%1, %2};" : "=l"(r) : "f"(lo), "f"(hi));
    return r;
}
__device__ __forceinline__ void unpack2(unsigned long long v, float& lo, float& hi) {
    asm("mov.b64 {%0, %1}, %2;" : "=f"(lo), "=f"(hi) : "l"(v));
}
__device__ __forceinline__ void ffma2(unsigned long long& d,
                                      unsigned long long a, unsigned long long b) {
    asm("fma.rn.f32x2 %0, %1, %2, %3;" : "=l"(d) : "l"(a), "l"(b), "l"(d));
}

// ---------------------------------------------------------------------------
// K1: x_l = X@W_l + b_l ; x_r = X@W_r + b_r, fp16 out, packed f32x2 FMA.
// X pre-packed (replicated) into u64 smem once; inner loop is pure FMA2.
// Halves the FFMA instruction count vs scalar (proj is issue-bound: R1 ncu
// showed 71% issue / 17.7% DRAM).
// ---------------------------------------------------------------------------
__global__ __launch_bounds__(256) void proj_kernel(
    const float* __restrict__ X,
    const float* __restrict__ Wl, const float* __restrict__ bl,
    const float* __restrict__ Wr, const float* __restrict__ br)
{
    __shared__ unsigned long long sx2[128 * IN_DIM];  // 16 KB
    const int c0 = threadIdx.x * 2;
    unsigned long long wl[IN_DIM], wr[IN_DIM];
#pragma unroll
    for (int k = 0; k < IN_DIM; k++) {
        wl[k] = pack2(Wl[k * HC + c0], Wl[k * HC + c0 + 1]);
        wr[k] = pack2(Wr[k * HC + c0], Wr[k * HC + c0 + 1]);
    }
    const unsigned long long bl2 = pack2(bl[c0], bl[c0 + 1]);
    const unsigned long long br2 = pack2(br[c0], br[c0 + 1]);

    const int n0 = blockIdx.x * 128;
    const int nmax = min(128, N_NODES - n0);

    for (int i = threadIdx.x; i < nmax * IN_DIM; i += blockDim.x) {
        const float v = X[(size_t)n0 * IN_DIM + i];
        sx2[i] = pack2(v, v);
    }
    __syncthreads();

    for (int n = 0; n < nmax; n++) {
        unsigned long long al = bl2, ar = br2;
#pragma unroll
        for (int k = 0; k < IN_DIM; k++) {
            const unsigned long long x2 = sx2[n * IN_DIM + k];
            ffma2(al, x2, wl[k]);
            ffma2(ar, x2, wr[k]);
        }
        float l0, l1, r0, r1;
        unpack2(al, l0, l1);
        unpack2(ar, r0, r1);
        const size_t o = ((size_t)(n0 + n) * HC + c0) >> 1;
        ((__half2*)g_xl)[o] = __floats2half2_rn(l0, l1);
        ((__half2*)g_xr)[o] = __floats2half2_rn(r0, r1);
    }
}

// ---------------------------------------------------------------------------
// CSR build: histogram -> single-block scan -> fill
// ---------------------------------------------------------------------------
__global__ __launch_bounds__(256) void hist_kernel(const int* __restrict__ idx)
{
    const int e = blockIdx.x * blockDim.x + threadIdx.x;
    if (e < N_EDGES) atomicAdd(&g_counts[idx[N_EDGES + e]], 1);
}

__global__ __launch_bounds__(1024) void scan_kernel()
{
    __shared__ int sp[1024];
    const int t = threadIdx.x;
    const int CH = (N_NODES + 1023) / 1024;
    const int base = t * CH;
    const int lim = min(CH, N_NODES - base);

    int sum = 0;
    for (int i = 0; i < lim; i++) sum += g_counts[base + i];
    sp[t] = sum;
    __syncthreads();
    for (int off = 1; off < 1024; off <<= 1) {
        int v = (t >= off) ? sp[t - off] : 0;
        __syncthreads();
        sp[t] += v;
        __syncthreads();
    }
    int run = (t > 0) ? sp[t - 1] : 0;
    for (int i = 0; i < lim; i++) {
        g_row[base + i] = run;
        g_cursor[base + i] = run;
        run += g_counts[base + i];
    }
    if (t == 0) g_row[N_NODES] = N_EDGES;
}

__global__ __launch_bounds__(256) void fill_kernel(const int* __restrict__ idx)
{
    const int e = blockIdx.x * blockDim.x + threadIdx.x;
    if (e >= N_EDGES) return;
    const int dst = idx[N_EDGES + e];
    const int pos = atomicAdd(&g_cursor[dst], 1);
    g_srcs[pos] = idx[e];
    g_dsts[pos] = dst;
}

// ---------------------------------------------------------------------------
// K2: edge-centric scores in CSR order (consecutive slots share dst -> L1/L2
// reuse of x_r row). One warp per CSR slot. Writes ex4 to g_ex[slot].
// No max-subtraction: scores are O(1), exp safe in fp32, softmax ratio exact.
// ---------------------------------------------------------------------------
__global__ __launch_bounds__(256) void score_kernel(const float* __restrict__ att)
{
    const int j = blockIdx.x * 8 + (threadIdx.x >> 5);
    if (j >= N_EDGES) return;
    const int lane = threadIdx.x & 31;
    const int src = g_srcs[j];
    const int dst = g_dsts[j];

    const uint2* __restrict__ xls = ((const uint2*)g_xl) + (size_t)src * 128;
    const uint2* __restrict__ xrs = ((const uint2*)g_xr) + (size_t)dst * 128;
    const float4* __restrict__ att4 = (const float4*)att;

    float eh[HEADS];
#pragma unroll
    for (int h = 0; h < HEADS; h++) {
        const uint2 ap = xls[h * 32 + lane];
        const uint2 bp = xrs[h * 32 + lane];
        const float2 a0 = __half22float2(*(const __half2*)&ap.x);
        const float2 a1 = __half22float2(*(const __half2*)&ap.y);
        const float2 b0 = __half22float2(*(const __half2*)&bp.x);
        const float2 b1 = __half22float2(*(const __half2*)&bp.y);

        const float4 w = __ldg(&att4[h * 32 + lane]);
        float s = lrelu(a0.x + b0.x) * w.x;
        s = fmaf(lrelu(a0.y + b0.y), w.y, s);
        s = fmaf(lrelu(a1.x + b1.x), w.z, s);
        s = fmaf(lrelu(a1.y + b1.y), w.w, s);
#pragma unroll
        for (int off = 16; off > 0; off >>= 1)
            s += __shfl_xor_sync(0xffffffffu, s, off);
        eh[h] = s;
    }

    if (lane == 0) {
        float4 ex;
        ex.x = __expf(eh[0]);
        ex.y = __expf(eh[1]);
        ex.z = __expf(eh[2]);
        ex.w = __expf(eh[3]);
        ((float4*)g_ex)[j] = ex;
    }
}

// ---------------------------------------------------------------------------
// K3: node-centric aggregate. One warp per node; loop over CSR slots:
// uniform ex4 + vector x_l gather + FMA. Registers only; single write with
// 1/den and bias fused. No atomics, no memset of out, no finalize pass.
// ---------------------------------------------------------------------------
__global__ __launch_bounds__(256) void aggregate_kernel(
    const float* __restrict__ bias, float* __restrict__ out)
{
    const int node = blockIdx.x * 8 + (threadIdx.x >> 5);
    if (node >= N_NODES) return;
    const int lane = threadIdx.x & 31;

    const int eb = g_row[node];
    const int ee = g_row[node + 1];

    float4 acc[HEADS];
#pragma unroll
    for (int h = 0; h < HEADS; h++) acc[h] = make_float4(0.f, 0.f, 0.f, 0.f);
    float4 den = make_float4(0.f, 0.f, 0.f, 0.f);

    for (int j = eb; j < ee; j++) {
        const int src = g_srcs[j];                       // lane-uniform
        const float4 ex = __ldg(&((const float4*)g_ex)[j]);
        const uint2* __restrict__ xlp = ((const uint2*)g_xl) + (size_t)src * 128;
#pragma unroll
        for (int h = 0; h < HEADS; h++) {
            const uint2 p = xlp[h * 32 + lane];
            const float2 f0 = __half22float2(*(const __half2*)&p.x);
            const float2 f1 = __half22float2(*(const __half2*)&p.y);
            const float s = (h == 0) ? ex.x : (h == 1) ? ex.y : (h == 2) ? ex.z : ex.w;
            acc[h].x = fmaf(s, f0.x, acc[h].x);
            acc[h].y = fmaf(s, f0.y, acc[h].y);
            acc[h].z = fmaf(s, f1.x, acc[h].z);
            acc[h].w = fmaf(s, f1.y, acc[h].w);
        }
        den.x += ex.x; den.y += ex.y; den.z += ex.z; den.w += ex.w;
    }

    const float invd[HEADS] = {
        den.x > 0.f ? 1.0f / den.x : 0.f,
        den.y > 0.f ? 1.0f / den.y : 0.f,
        den.z > 0.f ? 1.0f / den.z : 0.f,
        den.w > 0.f ? 1.0f / den.w : 0.f
    };

    float4* op = ((float4*)out) + (size_t)node * (HC / 4);
#pragma unroll
    for (int h = 0; h < HEADS; h++) {
        const float4 b = __ldg(&((const float4*)bias)[h * 32 + lane]);
        float4 o;
        o.x = fmaf(acc[h].x, invd[h], b.x);
        o.y = fmaf(acc[h].y, invd[h], b.y);
        o.z = fmaf(acc[h].z, invd[h], b.z);
        o.w = fmaf(acc[h].w, invd[h], b.w);
        op[h * 32 + lane] = o;
    }
}

// ---------------------------------------------------------------------------
extern "C" void kernel_launch(void* const* d_in, const int* in_sizes, int n_in,
                              void* d_out, int out_size)
{
    const float* X    = (const float*)d_in[0];  // [N, 16]
    const int*   idx  = (const int*)  d_in[1];  // [2, E]
    const float* Wl   = (const float*)d_in[2];  // [16, 512]
    const float* bl   = (const float*)d_in[3];  // [512]
    const float* Wr   = (const float*)d_in[4];  // [16, 512]
    const float* br   = (const float*)d_in[5];  // [512]
    const float* att  = (const float*)d_in[6];  // [4, 128]
    const float* bias = (const float*)d_in[7];  // [512]
    float* out = (float*)d_out;                 // [N, 512]

    void* counts_ptr = nullptr;
    cudaGetSymbolAddress(&counts_ptr, g_counts);
    cudaMemsetAsync(counts_ptr, 0, N_NODES * sizeof(int), 0);

    proj_kernel<<<(N_NODES + 127) / 128, 256>>>(X, Wl, bl, Wr, br);
    hist_kernel<<<(N_EDGES + 255) / 256, 256>>>(idx);
    scan_kernel<<<1, 1024>>>();
    fill_kernel<<<(N_EDGES + 255) / 256, 256>>>(idx);
    score_kernel<<<(N_EDGES + 7) / 8, 256>>>(att);
    aggregate_kernel<<<(N_NODES + 7) / 8, 256>>>(bias, out);
}

// round 10
// speedup vs baseline: 1.0343x; 1.0343x over previous
#include <cuda_runtime.h>
#include <cuda_fp16.h>

#define N_NODES 100000
#define N_EDGES 500000
#define IN_DIM 16
#define HEADS 4
#define OUT_DIM 128
#define HC 512           // HEADS*OUT_DIM
#define NEG 0.2f

// Scratch (device globals: allocation-free per harness rules)
__device__ __half g_xl[(size_t)N_NODES * HC];    // 102.4 MB
__device__ __half g_xr[(size_t)N_NODES * HC];    // 102.4 MB
__device__ float  g_ex[(size_t)N_EDGES * HEADS]; // 8 MB, CSR slot order
__device__ float  g_y[(size_t)N_NODES * 64];     // normalized alpha-weighted X sums, 25.6 MB
__device__ float  g_gate[(size_t)N_NODES * HEADS]; // 1 if den>0 else 0
__device__ int    g_counts[N_NODES];
__device__ int    g_row[N_NODES + 1];
__device__ int    g_cursor[N_NODES];
__device__ int    g_srcs[N_EDGES];               // CSR: src per slot
__device__ int    g_dsts[N_EDGES];               // CSR: dst per slot

__device__ __forceinline__ float lrelu(float v) { return v > 0.f ? v : NEG * v; }

// packed f32x2 helpers (sm_103a; ptxas never auto-fuses these)
__device__ __forceinline__ unsigned long long pack2(float lo, float hi) {
    unsigned long long r;
    asm("mov.b64 %0, {%1, %2};" : "=l"(r) : "f"(lo), "f"(hi));
    return r;
}
__device__ __forceinline__ void unpack2(unsigned long long v, float& lo, float& hi) {
    asm("mov.b64 {%0, %1}, %2;" : "=f"(lo), "=f"(hi) : "l"(v));
}
__device__ __forceinline__ void ffma2(unsigned long long& d,
                                      unsigned long long a, unsigned long long b) {
    asm("fma.rn.f32x2 %0, %1, %2, %3;" : "=l"(d) : "l"(a), "l"(b), "l"(d));
}

// ---------------------------------------------------------------------------
// K1: x_l = X@W_l + b_l ; x_r = X@W_r + b_r, fp16 out, packed f32x2 FMA.
// (exact structure of the 475us-best version)
// ---------------------------------------------------------------------------
__global__ __launch_bounds__(256) void proj_kernel(
    const float* __restrict__ X,
    const float* __restrict__ Wl, const float* __restrict__ bl,
    const float* __restrict__ Wr, const float* __restrict__ br)
{
    __shared__ float sx[128 * IN_DIM];
    const int c0 = threadIdx.x * 2;
    unsigned long long wl[IN_DIM], wr[IN_DIM];
#pragma unroll
    for (int k = 0; k < IN_DIM; k++) {
        wl[k] = pack2(Wl[k * HC + c0], Wl[k * HC + c0 + 1]);
        wr[k] = pack2(Wr[k * HC + c0], Wr[k * HC + c0 + 1]);
    }
    const unsigned long long bl2 = pack2(bl[c0], bl[c0 + 1]);
    const unsigned long long br2 = pack2(br[c0], br[c0 + 1]);

    const int n0 = blockIdx.x * 128;
    const int nmax = min(128, N_NODES - n0);

    for (int i = threadIdx.x; i < nmax * IN_DIM; i += blockDim.x)
        sx[i] = X[(size_t)n0 * IN_DIM + i];
    __syncthreads();

    for (int n = 0; n < nmax; n++) {
        unsigned long long al = bl2, ar = br2;
#pragma unroll
        for (int k = 0; k < IN_DIM; k++) {
            const float xv = sx[n * IN_DIM + k];
            const unsigned long long x2 = pack2(xv, xv);
            ffma2(al, x2, wl[k]);
            ffma2(ar, x2, wr[k]);
        }
        float l0, l1, r0, r1;
        unpack2(al, l0, l1);
        unpack2(ar, r0, r1);
        const size_t o = ((size_t)(n0 + n) * HC + c0) >> 1;
        ((__half2*)g_xl)[o] = __floats2half2_rn(l0, l1);
        ((__half2*)g_xr)[o] = __floats2half2_rn(r0, r1);
    }
}

// ---------------------------------------------------------------------------
// CSR build: histogram -> single-block scan -> fill
// ---------------------------------------------------------------------------
__global__ __launch_bounds__(256) void hist_kernel(const int* __restrict__ idx)
{
    const int e = blockIdx.x * blockDim.x + threadIdx.x;
    if (e < N_EDGES) atomicAdd(&g_counts[idx[N_EDGES + e]], 1);
}

__global__ __launch_bounds__(1024) void scan_kernel()
{
    __shared__ int sp[1024];
    const int t = threadIdx.x;
    const int CH = (N_NODES + 1023) / 1024;
    const int base = t * CH;
    const int lim = min(CH, N_NODES - base);

    int sum = 0;
    for (int i = 0; i < lim; i++) sum += g_counts[base + i];
    sp[t] = sum;
    __syncthreads();
    for (int off = 1; off < 1024; off <<= 1) {
        int v = (t >= off) ? sp[t - off] : 0;
        __syncthreads();
        sp[t] += v;
        __syncthreads();
    }
    int run = (t > 0) ? sp[t - 1] : 0;
    for (int i = 0; i < lim; i++) {
        g_row[base + i] = run;
        g_cursor[base + i] = run;
        run += g_counts[base + i];
    }
    if (t == 0) g_row[N_NODES] = N_EDGES;
}

__global__ __launch_bounds__(256) void fill_kernel(const int* __restrict__ idx)
{
    const int e = blockIdx.x * blockDim.x + threadIdx.x;
    if (e >= N_EDGES) return;
    const int dst = idx[N_EDGES + e];
    const int pos = atomicAdd(&g_cursor[dst], 1);
    g_srcs[pos] = idx[e];
    g_dsts[pos] = dst;
}

// ---------------------------------------------------------------------------
// K2: edge-centric scores in CSR order. One warp per CSR slot. (unchanged)
// No max-subtraction: scores are O(1), exp safe in fp32, softmax ratio exact.
// ---------------------------------------------------------------------------
__global__ __launch_bounds__(256) void score_kernel(const float* __restrict__ att)
{
    const int j = blockIdx.x * 8 + (threadIdx.x >> 5);
    if (j >= N_EDGES) return;
    const int lane = threadIdx.x & 31;
    const int src = g_srcs[j];
    const int dst = g_dsts[j];

    const uint2* __restrict__ xls = ((const uint2*)g_xl) + (size_t)src * 128;
    const uint2* __restrict__ xrs = ((const uint2*)g_xr) + (size_t)dst * 128;
    const float4* __restrict__ att4 = (const float4*)att;

    float eh[HEADS];
#pragma unroll
    for (int h = 0; h < HEADS; h++) {
        const uint2 ap = xls[h * 32 + lane];
        const uint2 bp = xrs[h * 32 + lane];
        const float2 a0 = __half22float2(*(const __half2*)&ap.x);
        const float2 a1 = __half22float2(*(const __half2*)&ap.y);
        const float2 b0 = __half22float2(*(const __half2*)&bp.x);
        const float2 b1 = __half22float2(*(const __half2*)&bp.y);

        const float4 w = __ldg(&att4[h * 32 + lane]);
        float s = lrelu(a0.x + b0.x) * w.x;
        s = fmaf(lrelu(a0.y + b0.y), w.y, s);
        s = fmaf(lrelu(a1.x + b1.x), w.z, s);
        s = fmaf(lrelu(a1.y + b1.y), w.w, s);
#pragma unroll
        for (int off = 16; off > 0; off >>= 1)
            s += __shfl_xor_sync(0xffffffffu, s, off);
        eh[h] = s;
    }

    if (lane == 0) {
        float4 ex;
        ex.x = __expf(eh[0]);
        ex.y = __expf(eh[1]);
        ex.z = __expf(eh[2]);
        ex.w = __expf(eh[3]);
        ((float4*)g_ex)[j] = ex;
    }
}

// ---------------------------------------------------------------------------
// K3: X-space aggregation (out = (sum alpha X[src]) @ W_l + b_l is linear!).
// One warp per node. Lane (k = lane&15, half = lane>>4) accumulates
// y[half][k] and y[2+half][k]; X is 6.4 MB -> fully L2-resident gathers.
// Writes NORMALIZED y (y/den) and a per-head gate (den>0).
// ---------------------------------------------------------------------------
__global__ __launch_bounds__(256) void aggregate_kernel(const float* __restrict__ X)
{
    const int node = blockIdx.x * 8 + (threadIdx.x >> 5);
    if (node >= N_NODES) return;
    const int lane = threadIdx.x & 31;
    const int k = lane & 15;
    const int half = lane >> 4;

    const int eb = g_row[node];
    const int ee = g_row[node + 1];

    float yA = 0.f, yB = 0.f;             // heads: half and 2+half
    float4 den = make_float4(0.f, 0.f, 0.f, 0.f);

    for (int j = eb; j < ee; j++) {
        const int src = g_srcs[j];                         // lane-uniform
        const float4 ex = __ldg(&((const float4*)g_ex)[j]);
        const float xv = __ldg(&X[(size_t)src * IN_DIM + k]);  // broadcast halves
        const float wA = half ? ex.y : ex.x;
        const float wB = half ? ex.w : ex.z;
        yA = fmaf(wA, xv, yA);
        yB = fmaf(wB, xv, yB);
        den.x += ex.x; den.y += ex.y; den.z += ex.z; den.w += ex.w;
    }

    const float dA = half ? den.y : den.x;
    const float dB = half ? den.w : den.z;
    const float iA = (dA > 0.f) ? (1.0f / dA) : 0.f;
    const float iB = (dB > 0.f) ? (1.0f / dB) : 0.f;

    // layout: g_y[node][h*16 + k]; heads 0,1 occupy lanes 0..31 directly
    g_y[(size_t)node * 64 + lane]      = yA * iA;
    g_y[(size_t)node * 64 + 32 + lane] = yB * iB;
    if (lane < 4) {
        const float d = (lane == 0) ? den.x : (lane == 1) ? den.y
                      : (lane == 2) ? den.z : den.w;
        g_gate[node * HEADS + lane] = (d > 0.f) ? 1.f : 0.f;
    }
}

// ---------------------------------------------------------------------------
// K4: out[node] = y_norm[node] @ W_l + gate*b_l + bias (proj-shaped stream).
// Thread owns 2 adjacent cols; 128 nodes per block staged via smem.
// ---------------------------------------------------------------------------
__global__ __launch_bounds__(256) void outproj_kernel(
    const float* __restrict__ Wl, const float* __restrict__ bl,
    const float* __restrict__ bias, float* __restrict__ out)
{
    __shared__ float sy[128 * 64];   // 32 KB
    __shared__ float sg[128 * HEADS];
    const int c0 = threadIdx.x * 2;
    const int hh = c0 >> 7;          // head of both columns

    unsigned long long w[IN_DIM];
#pragma unroll
    for (int k = 0; k < IN_DIM; k++)
        w[k] = pack2(Wl[k * HC + c0], Wl[k * HC + c0 + 1]);
    const float bl0 = bl[c0], bl1 = bl[c0 + 1];
    const float bs0 = bias[c0], bs1 = bias[c0 + 1];

    const int n0 = blockIdx.x * 128;
    const int nmax = min(128, N_NODES - n0);

    for (int i = threadIdx.x; i < nmax * 64; i += blockDim.x)
        sy[i] = g_y[(size_t)n0 * 64 + i];
    for (int i = threadIdx.x; i < nmax * HEADS; i += blockDim.x)
        sg[i] = g_gate[n0 * HEADS + i];
    __syncthreads();

    for (int n = 0; n < nmax; n++) {
        const float gate = sg[n * HEADS + hh];
        unsigned long long acc = pack2(fmaf(gate, bl0, bs0), fmaf(gate, bl1, bs1));
        const float* yrow = sy + n * 64 + hh * 16;
#pragma unroll
        for (int k = 0; k < IN_DIM; k++) {
            const float yv = yrow[k];
            ffma2(acc, pack2(yv, yv), w[k]);
        }
        float o0, o1;
        unpack2(acc, o0, o1);
        ((float2*)out)[((size_t)(n0 + n) * HC + c0) >> 1] = make_float2(o0, o1);
    }
}

// ---------------------------------------------------------------------------
extern "C" void kernel_launch(void* const* d_in, const int* in_sizes, int n_in,
                              void* d_out, int out_size)
{
    const float* X    = (const float*)d_in[0];  // [N, 16]
    const int*   idx  = (const int*)  d_in[1];  // [2, E]
    const float* Wl   = (const float*)d_in[2];  // [16, 512]
    const float* bl   = (const float*)d_in[3];  // [512]
    const float* Wr   = (const float*)d_in[4];  // [16, 512]
    const float* br   = (const float*)d_in[5];  // [512]
    const float* att  = (const float*)d_in[6];  // [4, 128]
    const float* bias = (const float*)d_in[7];  // [512]
    float* out = (float*)d_out;                 // [N, 512]

    void* counts_ptr = nullptr;
    cudaGetSymbolAddress(&counts_ptr, g_counts);
    cudaMemsetAsync(counts_ptr, 0, N_NODES * sizeof(int), 0);

    proj_kernel<<<(N_NODES + 127) / 128, 256>>>(X, Wl, bl, Wr, br);
    hist_kernel<<<(N_EDGES + 255) / 256, 256>>>(idx);
    scan_kernel<<<1, 1024>>>();
    fill_kernel<<<(N_EDGES + 255) / 256, 256>>>(idx);
    score_kernel<<<(N_EDGES + 7) / 8, 256>>>(att);
    aggregate_kernel<<<(N_NODES + 7) / 8, 256>>>(X);
    outproj_kernel<<<(N_NODES + 127) / 128, 256>>>(Wl, bl, bias, out);
}